// round 1
// baseline (speedup 1.0000x reference)
#include <cuda_runtime.h>

#define H 512
#define W 512
#define C 32
#define BATCH 4

// Scratch (device globals — no allocation)
__device__ float g_wf[C * C * 9];     // BN-folded conv weights [co][ci][k]
__device__ float g_bias[C];           // BN-folded bias per output channel
__device__ float g_x[BATCH * H * W];  // intermediate 1-channel map

// ---- packed f32x2 helpers (Blackwell) ----
__device__ __forceinline__ unsigned long long pk2(float lo, float hi) {
    unsigned long long r;
    asm("mov.b64 %0, {%1,%2};" : "=l"(r) : "f"(lo), "f"(hi));
    return r;
}
__device__ __forceinline__ unsigned long long ffma2(unsigned long long a,
                                                    unsigned long long b,
                                                    unsigned long long c) {
    unsigned long long d;
    asm("fma.rn.f32x2 %0, %1, %2, %3;" : "=l"(d) : "l"(a), "l"(b), "l"(c));
    return d;
}

// ---- K0: fold BN into conv weights ----
__global__ void fold_kernel(const float* __restrict__ w_conv,
                            const float* __restrict__ gamma,
                            const float* __restrict__ beta,
                            const float* __restrict__ mean,
                            const float* __restrict__ var) {
    int i = blockIdx.x * blockDim.x + threadIdx.x;
    if (i < C * C * 9) {
        int co = i / (C * 9);
        float inv = gamma[co] * rsqrtf(var[co] + 1e-5f);
        g_wf[i] = w_conv[i] * inv;
    }
    if (i < C) {
        float inv = gamma[i] * rsqrtf(var[i] + 1e-5f);
        g_bias[i] = beta[i] - mean[i] * inv;
    }
}

// ---- K1: conv3x3 + BN + SiLU + 1x1 -> g_x ----
// Tile 64x8 pixels. 256 threads. Thread = 8 pixels (one row, 8 cols, 4 f32x2
// pairs) x 8 output channels (4-way co split over threadIdx>>6).
__global__ __launch_bounds__(256) void stage1_kernel(
    const float* __restrict__ cen,
    const float* __restrict__ w1x1,
    const float* __restrict__ b1x1) {
    __shared__ float wsm[C * 8 * 9];   // weights chunk [co][cil][k]   (9 KB)
    __shared__ float xsm[8 * 10 * 66]; // input chunk  [cil][yy][xx]   (21 KB)
    __shared__ float psm[4 * 512];     // co-split partials            (8 KB)

    const int t = threadIdx.x;
    const int cosub = t >> 6;       // 0..3 -> co group of 8
    const int g = t & 63;
    const int row = g >> 3;         // 0..7
    const int c0 = (g & 7) * 8;     // 0,8,..,56
    const int gx0 = blockIdx.x * 64;
    const int gy0 = blockIdx.y * 8;
    const int b = blockIdx.z;

    unsigned long long acc[8][4];
#pragma unroll
    for (int cc = 0; cc < 8; cc++)
#pragma unroll
        for (int q = 0; q < 4; q++) acc[cc][q] = 0ull;

    for (int ci0 = 0; ci0 < C; ci0 += 8) {
        __syncthreads();
        // load weight chunk: 32 co x 8 ci x 9
        for (int i = t; i < C * 8 * 9; i += 256) {
            int co = i / 72;
            int r = i - co * 72;  // cil*9 + k
            wsm[i] = g_wf[co * (C * 9) + ci0 * 9 + r];
        }
        // load input chunk with 1-halo, zero padded
        for (int i = t; i < 8 * 10 * 66; i += 256) {
            int cil = i / 660;
            int rr = i - cil * 660;
            int yy = rr / 66;
            int xx = rr - yy * 66;
            int gy = gy0 + yy - 1;
            int gx = gx0 + xx - 1;
            float v = 0.0f;
            if ((unsigned)gy < (unsigned)H && (unsigned)gx < (unsigned)W)
                v = cen[(((size_t)b * C + ci0 + cil) * H + gy) * W + gx];
            xsm[i] = v;
        }
        __syncthreads();

#pragma unroll 1
        for (int cil = 0; cil < 8; cil++) {
            const float* xb = &xsm[cil * 660 + row * 66 + c0];
            unsigned long long P[3][9];
#pragma unroll
            for (int r = 0; r < 3; r++) {
                float xv[10];
#pragma unroll
                for (int u = 0; u < 10; u++) xv[u] = xb[r * 66 + u];
#pragma unroll
                for (int o = 0; o < 9; o++) P[r][o] = pk2(xv[o], xv[o + 1]);
            }
            const float* wb = &wsm[(cosub * 8) * 72 + cil * 9];
#pragma unroll
            for (int cc = 0; cc < 8; cc++) {
#pragma unroll
                for (int kh = 0; kh < 3; kh++) {
#pragma unroll
                    for (int kw = 0; kw < 3; kw++) {
                        float w = wb[cc * 72 + kh * 3 + kw];
                        unsigned long long w2 = pk2(w, w);
#pragma unroll
                        for (int q = 0; q < 4; q++)
                            acc[cc][q] = ffma2(w2, P[kh][2 * q + kw], acc[cc][q]);
                    }
                }
            }
        }
    }

    // epilogue: bias + SiLU + 1x1 partial over this thread's 8 cos
    float part[8];
#pragma unroll
    for (int p = 0; p < 8; p++) part[p] = 0.f;
#pragma unroll
    for (int cc = 0; cc < 8; cc++) {
        int co = cosub * 8 + cc;
        float bsv = g_bias[co];
        float w1 = __ldg(&w1x1[co]);
#pragma unroll
        for (int q = 0; q < 4; q++) {
            float v0, v1;
            asm("mov.b64 {%0,%1}, %2;" : "=f"(v0), "=f"(v1) : "l"(acc[cc][q]));
            v0 += bsv;
            v1 += bsv;
            float s0 = v0 / (1.f + __expf(-v0));
            float s1 = v1 / (1.f + __expf(-v1));
            part[2 * q] += w1 * s0;
            part[2 * q + 1] += w1 * s1;
        }
    }
#pragma unroll
    for (int p = 0; p < 8; p++)
        psm[cosub * 512 + row * 64 + c0 + p] = part[p];
    __syncthreads();

    float b1 = __ldg(b1x1);
    for (int p = t; p < 512; p += 256) {
        float s = psm[p] + psm[512 + p] + psm[1024 + p] + psm[1536 + p] + b1;
        int rr = p >> 6;
        int ccol = p & 63;
        g_x[((size_t)b * H + gy0 + rr) * W + gx0 + ccol] = s;
    }
}

// ---- K2: shifted-difference attention + gate all channels ----
__device__ __forceinline__ float ldx(const float* __restrict__ X, int i, int j) {
    if ((unsigned)i < (unsigned)H && (unsigned)j < (unsigned)W)
        return __ldg(X + i * W + j);
    return 0.f;
}

__global__ __launch_bounds__(128) void stage2_kernel(
    const float* __restrict__ cen, float* __restrict__ out) {
    const int i = blockIdx.x;  // row
    const int b = blockIdx.y;  // batch
    const int j0 = threadIdx.x * 4;
    const float* X = g_x + (size_t)b * H * W;

    float4 av;
    float* avp = (float*)&av;
#pragma unroll
    for (int p = 0; p < 4; p++) {
        int j = j0 + p;
        float x0 = X[i * W + j];
        float ms[2];
#pragma unroll
        for (int si = 0; si < 2; si++) {
            int s = si ? 3 : 1;
            float p0 = (x0 - ldx(X, i - s, j - s)) * (x0 - ldx(X, i + s, j + s));
            float p1 = (x0 - ldx(X, i - s, j))     * (x0 - ldx(X, i + s, j));
            float p2 = (x0 - ldx(X, i - s, j + s)) * (x0 - ldx(X, i + s, j - s));
            float p3 = (x0 - ldx(X, i, j - s))     * (x0 - ldx(X, i, j + s));
            ms[si] = fminf(fminf(p0, p1), fminf(p2, p3));
        }
        float att_in = (fmaxf(ms[0], ms[1]) + 0.5f * (ms[0] + ms[1])) * 0.5f;
        float r = fmaxf(att_in, 0.f);
        avp[p] = 1.f / (1.f + __expf(-r));
    }

    size_t base = ((size_t)b * C * H + i) * W + j0;
#pragma unroll
    for (int c = 0; c < C; c++) {
        const float4 v = *(const float4*)(cen + base + (size_t)c * H * W);
        float4 o;
        o.x = v.x * av.x;
        o.y = v.y * av.y;
        o.z = v.z * av.z;
        o.w = v.w * av.w;
        *(float4*)(out + base + (size_t)c * H * W) = o;
    }
}

extern "C" void kernel_launch(void* const* d_in, const int* in_sizes, int n_in,
                              void* d_out, int out_size) {
    const float* cen    = (const float*)d_in[0];
    const float* w_conv = (const float*)d_in[1];
    const float* gamma  = (const float*)d_in[2];
    const float* beta   = (const float*)d_in[3];
    const float* mean   = (const float*)d_in[4];
    const float* var    = (const float*)d_in[5];
    const float* w1x1   = (const float*)d_in[6];
    const float* b1x1   = (const float*)d_in[7];
    float* out = (float*)d_out;

    fold_kernel<<<36, 256>>>(w_conv, gamma, beta, mean, var);
    stage1_kernel<<<dim3(8, 64, BATCH), 256>>>(cen, w1x1, b1x1);
    stage2_kernel<<<dim3(H, BATCH), 128>>>(cen, out);
}

// round 3
// speedup vs baseline: 1.5452x; 1.5452x over previous
#include <cuda_runtime.h>
#include <cuda_bf16.h>
#include <cstdint>

#define H 512
#define W 512
#define C 32
#define BATCH 4

// ---- device scratch (no allocation) ----
__device__ float g_wf[C * C * 9];     // BN-folded conv weights [co][ci][pos]
__device__ float g_bias[C];
__device__ float g_x[BATCH * H * W];  // intermediate 1-channel map

// ---- smem layout (dynamic) ----
// A ring: 4 slots, each [x:130][ 64B hi(ci32) | 64B lo(ci32) | 16B pad ] = 130*144
#define A_STRIDE   18720
#define OFF_WB     (4 * A_STRIDE)          // 74880
#define WB_STRIDE  1168                    // 576 bf16 (hi 288 + lo 288) + 16B pad
#define OFF_BIAS   (OFF_WB + C * WB_STRIDE)  // 112256
#define OFF_W1     (OFF_BIAS + 128)
#define OFF_B1     (OFF_W1 + 128)
#define SMEM_TOTAL (OFF_B1 + 128)

__device__ __forceinline__ uint32_t smem_u32(const void* p) {
    uint32_t a;
    asm("{ .reg .u64 t; cvta.to.shared.u64 t, %1; cvt.u32.u64 %0, t; }" : "=r"(a) : "l"(p));
    return a;
}

__device__ __forceinline__ void ldsm_x4(uint32_t addr, uint32_t& r0, uint32_t& r1,
                                        uint32_t& r2, uint32_t& r3) {
    asm volatile("ldmatrix.sync.aligned.m8n8.x4.shared.b16 {%0,%1,%2,%3}, [%4];"
                 : "=r"(r0), "=r"(r1), "=r"(r2), "=r"(r3) : "r"(addr));
}

__device__ __forceinline__ void mma_bf16(float* c, const uint32_t* a, uint32_t b0,
                                         uint32_t b1) {
    asm volatile(
        "mma.sync.aligned.m16n8k16.row.col.f32.bf16.bf16.f32 "
        "{%0,%1,%2,%3}, {%4,%5,%6,%7}, {%8,%9}, {%0,%1,%2,%3};"
        : "+f"(c[0]), "+f"(c[1]), "+f"(c[2]), "+f"(c[3])
        : "r"(a[0]), "r"(a[1]), "r"(a[2]), "r"(a[3]), "r"(b0), "r"(b1));
}

// ---- K0: fold BN into conv weights ----
__global__ void fold_kernel(const float* __restrict__ w_conv,
                            const float* __restrict__ gamma,
                            const float* __restrict__ beta,
                            const float* __restrict__ mean,
                            const float* __restrict__ var) {
    int i = blockIdx.x * blockDim.x + threadIdx.x;
    if (i < C * C * 9) {
        int co = i / (C * 9);
        float inv = gamma[co] * rsqrtf(var[co] + 1e-5f);
        g_wf[i] = w_conv[i] * inv;
    }
    if (i < C) {
        float inv = gamma[i] * rsqrtf(var[i] + 1e-5f);
        g_bias[i] = beta[i] - mean[i] * inv;
    }
}

// load one input row into ring slot (yin+4)&3; zero-fills OOB
__device__ __forceinline__ void load_row(char* smem, const float* __restrict__ cen,
                                         int b, int yin, int x0, int t) {
    char* Ab = smem + ((yin + 4) & 3) * A_STRIDE;
    const bool rowok = (unsigned)yin < (unsigned)H;
    for (int e = t; e < 130 * C; e += 256) {
        int ci = e / 130;
        int x = e - ci * 130;
        int gx = x0 - 1 + x;
        float v = 0.f;
        if (rowok && (unsigned)gx < (unsigned)W)
            v = cen[(((size_t)b * C + ci) * H + yin) * W + gx];
        __nv_bfloat16 hb = __float2bfloat16(v);
        __nv_bfloat16 lb = __float2bfloat16(v - __bfloat162float(hb));
        *reinterpret_cast<__nv_bfloat16*>(Ab + x * 144 + ci * 2) = hb;
        *reinterpret_cast<__nv_bfloat16*>(Ab + x * 144 + 64 + ci * 2) = lb;
    }
}

// ---- K1: implicit-GEMM conv3x3 (bf16-split mma.sync) + BN + SiLU + 1x1 ----
__global__ __launch_bounds__(256) void stage1_kernel(
    const float* __restrict__ cen,
    const float* __restrict__ w1x1,
    const float* __restrict__ b1x1) {
    extern __shared__ __align__(128) char smem[];
    float* biasS = (float*)(smem + OFF_BIAS);
    float* w1S = (float*)(smem + OFF_W1);
    float* b1S = (float*)(smem + OFF_B1);

    const int t = threadIdx.x;
    const int lane = t & 31;
    const int wrp = t >> 5;
    const int x0 = blockIdx.x * 128;
    const int y0 = blockIdx.y * 64;
    const int b = blockIdx.z;
    const uint32_t sbase = smem_u32(smem);

    // weights -> WB[co][k] bf16 (hi: k=pos*32+ci, lo at +288)
    for (int i = t; i < C * C * 9; i += 256) {
        int co = i / 288;
        int rem = i - co * 288;
        int ci = rem / 9;
        int pos = rem - ci * 9;
        float w = g_wf[i];
        __nv_bfloat16 hb = __float2bfloat16(w);
        __nv_bfloat16 lb = __float2bfloat16(w - __bfloat162float(hb));
        char* p = smem + OFF_WB + co * WB_STRIDE + (pos * 32 + ci) * 2;
        *reinterpret_cast<__nv_bfloat16*>(p) = hb;
        *reinterpret_cast<__nv_bfloat16*>(p + 576) = lb;
    }
    if (t < C) {
        biasS[t] = g_bias[t];
        w1S[t] = __ldg(&w1x1[t]);
    }
    if (t == 0) b1S[0] = __ldg(b1x1);

    // preload rows y0-1, y0
    load_row(smem, cen, b, y0 - 1, x0, t);
    load_row(smem, cen, b, y0, x0, t);

    // per-warp geometry: row r = wrp>>2, px0 = (wrp&3)*32
    const int r = wrp >> 2;
    const int px0 = (wrp & 3) * 32;

    // lane-invariant pieces of ldmatrix addresses
    // A: row-of-matrix = pixel; lanes 0-15 -> px (lane&15); lanes>=16 -> +16B (k hi half)
    const uint32_t aLane = (uint32_t)((px0 + (lane & 15)) * 144 + ((lane & 16) ? 16 : 0));
    // B: row = nt*8 + (lane&7) + ((lane&16)?8:0); col += ((lane&8)?16:0)
    const uint32_t bLane = sbase + OFF_WB +
                           (uint32_t)(((lane & 7) + ((lane & 16) ? 8 : 0)) * WB_STRIDE +
                                      ((lane & 8) ? 16 : 0));

    for (int y = y0; y < y0 + 64; y += 2) {
        __syncthreads();  // prior iter finished reading slots we overwrite
        load_row(smem, cen, b, y + 1, x0, t);
        load_row(smem, cen, b, y + 2, x0, t);
        __syncthreads();

        float Cfr[2][4][4];
#pragma unroll
        for (int mt = 0; mt < 2; mt++)
#pragma unroll
            for (int nt = 0; nt < 4; nt++)
#pragma unroll
                for (int q = 0; q < 4; q++) Cfr[mt][nt][q] = 0.f;

        const int yr = y + r;  // this warp's output row
#pragma unroll
        for (int kh = 0; kh < 3; kh++) {
            const uint32_t aRing = sbase + ((yr - 1 + kh + 4) & 3) * A_STRIDE + aLane;
#pragma unroll
            for (int kw = 0; kw < 3; kw++) {
                const int pos = kh * 3 + kw;
                const uint32_t aBase = aRing + kw * 144;
                const uint32_t bCol = pos * 64;
#pragma unroll
                for (int cih = 0; cih < 2; cih++) {
                    uint32_t Ah[2][4], Al[2][4], Bh[8], Bl[8];
                    const uint32_t aOff = aBase + cih * 32;
#pragma unroll
                    for (int mt = 0; mt < 2; mt++) {
                        ldsm_x4(aOff + mt * (16 * 144), Ah[mt][0], Ah[mt][1], Ah[mt][2],
                                Ah[mt][3]);
                        ldsm_x4(aOff + mt * (16 * 144) + 64, Al[mt][0], Al[mt][1],
                                Al[mt][2], Al[mt][3]);
                    }
                    const uint32_t bOff = bLane + bCol + cih * 32;
                    ldsm_x4(bOff, Bh[0], Bh[1], Bh[2], Bh[3]);
                    ldsm_x4(bOff + 2 * 8 * WB_STRIDE, Bh[4], Bh[5], Bh[6], Bh[7]);
                    ldsm_x4(bOff + 576, Bl[0], Bl[1], Bl[2], Bl[3]);
                    ldsm_x4(bOff + 576 + 2 * 8 * WB_STRIDE, Bl[4], Bl[5], Bl[6], Bl[7]);
                    // term 1: ah*bh
#pragma unroll
                    for (int mt = 0; mt < 2; mt++)
#pragma unroll
                        for (int nt = 0; nt < 4; nt++)
                            mma_bf16(Cfr[mt][nt], Ah[mt], Bh[nt * 2], Bh[nt * 2 + 1]);
                    // term 2: ah*bl
#pragma unroll
                    for (int mt = 0; mt < 2; mt++)
#pragma unroll
                        for (int nt = 0; nt < 4; nt++)
                            mma_bf16(Cfr[mt][nt], Ah[mt], Bl[nt * 2], Bl[nt * 2 + 1]);
                    // term 3: al*bh
#pragma unroll
                    for (int mt = 0; mt < 2; mt++)
#pragma unroll
                        for (int nt = 0; nt < 4; nt++)
                            mma_bf16(Cfr[mt][nt], Al[mt], Bh[nt * 2], Bh[nt * 2 + 1]);
                }
            }
        }

        // epilogue: bias + SiLU + 1x1 dot over co, reduce across quad lanes
        const int g = lane >> 2;
        const int tid4 = lane & 3;
        const float b1v = b1S[0];
#pragma unroll
        for (int mt = 0; mt < 2; mt++) {
            float sA = 0.f, sB = 0.f;
#pragma unroll
            for (int nt = 0; nt < 4; nt++) {
                int co0 = nt * 8 + 2 * tid4;
                float bs0 = biasS[co0], bs1 = biasS[co0 + 1];
                float w10 = w1S[co0], w11 = w1S[co0 + 1];
                float v0 = Cfr[mt][nt][0] + bs0;
                float v1 = Cfr[mt][nt][1] + bs1;
                float v2 = Cfr[mt][nt][2] + bs0;
                float v3 = Cfr[mt][nt][3] + bs1;
                sA = fmaf(w10, __fdividef(v0, 1.f + __expf(-v0)), sA);
                sA = fmaf(w11, __fdividef(v1, 1.f + __expf(-v1)), sA);
                sB = fmaf(w10, __fdividef(v2, 1.f + __expf(-v2)), sB);
                sB = fmaf(w11, __fdividef(v3, 1.f + __expf(-v3)), sB);
            }
            sA += __shfl_xor_sync(0xFFFFFFFF, sA, 1);
            sA += __shfl_xor_sync(0xFFFFFFFF, sA, 2);
            sB += __shfl_xor_sync(0xFFFFFFFF, sB, 1);
            sB += __shfl_xor_sync(0xFFFFFFFF, sB, 2);
            if (tid4 == 0) {
                int px = px0 + mt * 16;
                float* gp = &g_x[((size_t)b * H + yr) * W + x0 + px];
                gp[g] = sA + b1v;
                gp[g + 8] = sB + b1v;
            }
        }
    }
}

// ---- K2: shifted-difference attention + gate all channels ----
__device__ __forceinline__ float ldx(const float* __restrict__ X, int i, int j) {
    if ((unsigned)i < (unsigned)H && (unsigned)j < (unsigned)W)
        return __ldg(X + i * W + j);
    return 0.f;
}

__global__ __launch_bounds__(128) void stage2_kernel(
    const float* __restrict__ cen, float* __restrict__ out) {
    const int i = blockIdx.x;
    const int b = blockIdx.y;
    const int j0 = threadIdx.x * 4;
    const float* X = g_x + (size_t)b * H * W;

    float4 av;
    float* avp = (float*)&av;
#pragma unroll
    for (int p = 0; p < 4; p++) {
        int j = j0 + p;
        float x0 = X[i * W + j];
        float ms[2];
#pragma unroll
        for (int si = 0; si < 2; si++) {
            int s = si ? 3 : 1;
            float p0 = (x0 - ldx(X, i - s, j - s)) * (x0 - ldx(X, i + s, j + s));
            float p1 = (x0 - ldx(X, i - s, j)) * (x0 - ldx(X, i + s, j));
            float p2 = (x0 - ldx(X, i - s, j + s)) * (x0 - ldx(X, i + s, j - s));
            float p3 = (x0 - ldx(X, i, j - s)) * (x0 - ldx(X, i, j + s));
            ms[si] = fminf(fminf(p0, p1), fminf(p2, p3));
        }
        float att_in = (fmaxf(ms[0], ms[1]) + 0.5f * (ms[0] + ms[1])) * 0.5f;
        float rr = fmaxf(att_in, 0.f);
        avp[p] = 1.f / (1.f + __expf(-rr));
    }

    size_t base = ((size_t)b * C * H + i) * W + j0;
#pragma unroll
    for (int c = 0; c < C; c++) {
        const float4 v = *(const float4*)(cen + base + (size_t)c * H * W);
        float4 o;
        o.x = v.x * av.x;
        o.y = v.y * av.y;
        o.z = v.z * av.z;
        o.w = v.w * av.w;
        *(float4*)(out + base + (size_t)c * H * W) = o;
    }
}

extern "C" void kernel_launch(void* const* d_in, const int* in_sizes, int n_in,
                              void* d_out, int out_size) {
    const float* cen = (const float*)d_in[0];
    const float* w_conv = (const float*)d_in[1];
    const float* gamma = (const float*)d_in[2];
    const float* beta = (const float*)d_in[3];
    const float* mean = (const float*)d_in[4];
    const float* var = (const float*)d_in[5];
    const float* w1x1 = (const float*)d_in[6];
    const float* b1x1 = (const float*)d_in[7];
    float* out = (float*)d_out;

    cudaFuncSetAttribute(stage1_kernel, cudaFuncAttributeMaxDynamicSharedMemorySize,
                         SMEM_TOTAL);

    fold_kernel<<<36, 256>>>(w_conv, gamma, beta, mean, var);
    stage1_kernel<<<dim3(4, 8, BATCH), 256, SMEM_TOTAL>>>(cen, w1x1, b1x1);
    stage2_kernel<<<dim3(H, BATCH), 128>>>(cen, out);
}

// round 6
// speedup vs baseline: 3.0945x; 2.0027x over previous
#include <cuda_runtime.h>
#include <cuda_fp16.h>
#include <cstdint>

#define H 512
#define W 512
#define C 32
#define BATCH 4

// ---- device scratch (no allocation) ----
__device__ float g_x[BATCH * H * W];  // intermediate 1-channel map

// ---- smem layout (dynamic) ----
// A ring: 6 slots, each [x:130][ci:32] fp16, x-stride 80B (conflict-free ldsm)
#define A_XSTR     80
#define A_SLOT     (130 * A_XSTR)           // 10400
#define OFF_WB     (6 * A_SLOT)             // 62400
#define WB_STRIDE  1168                     // hi 288*2 + lo 288*2 + 16 pad
#define OFF_BIAS   (OFF_WB + C * WB_STRIDE) // 99776
#define OFF_W1     (OFF_BIAS + 128)
#define OFF_B1     (OFF_W1 + 128)
#define SMEM_TOTAL (OFF_B1 + 128)

__device__ __forceinline__ uint32_t smem_u32(const void* p) {
    uint32_t a;
    asm("{ .reg .u64 t; cvta.to.shared.u64 t, %1; cvt.u32.u64 %0, t; }" : "=r"(a) : "l"(p));
    return a;
}

__device__ __forceinline__ void ldsm_x4(uint32_t addr, uint32_t& r0, uint32_t& r1,
                                        uint32_t& r2, uint32_t& r3) {
    asm volatile("ldmatrix.sync.aligned.m8n8.x4.shared.b16 {%0,%1,%2,%3}, [%4];"
                 : "=r"(r0), "=r"(r1), "=r"(r2), "=r"(r3) : "r"(addr));
}

__device__ __forceinline__ void mma_f16(float* c, const uint32_t* a, uint32_t b0,
                                        uint32_t b1) {
    asm volatile(
        "mma.sync.aligned.m16n8k16.row.col.f32.f16.f16.f32 "
        "{%0,%1,%2,%3}, {%4,%5,%6,%7}, {%8,%9}, {%0,%1,%2,%3};"
        : "+f"(c[0]), "+f"(c[1]), "+f"(c[2]), "+f"(c[3])
        : "r"(a[0]), "r"(a[1]), "r"(a[2]), "r"(a[3]), "r"(b0), "r"(b1));
}

// LDG one input row into registers (17 per thread)
__device__ __forceinline__ void ldg_row(const float* __restrict__ cen, int b, int yin,
                                        int x0, int t, float* va) {
    const bool ok = (unsigned)yin < (unsigned)H;
#pragma unroll
    for (int i = 0; i < 17; i++) {
        int e = t + i * 256;
        float v = 0.f;
        if (e < 4160 && ok) {
            int ci = e / 130;
            int x = e - ci * 130;
            int gx = x0 - 1 + x;
            if ((unsigned)gx < (unsigned)W)
                v = __ldg(&cen[(((size_t)b * C + ci) * H + yin) * W + gx]);
        }
        va[i] = v;
    }
}

// convert + store one row into its ring slot
__device__ __forceinline__ void sts_row(char* smem, int yin, int t, const float* va) {
    char* Ab = smem + ((yin + 6) % 6) * A_SLOT;
#pragma unroll
    for (int i = 0; i < 17; i++) {
        int e = t + i * 256;
        if (e < 4160) {
            int ci = e / 130;
            int x = e - ci * 130;
            *reinterpret_cast<__half*>(Ab + x * A_XSTR + ci * 2) = __float2half(va[i]);
        }
    }
}

// ---- K1: implicit-GEMM conv3x3 (fp16 2-term mma.sync) + BN + SiLU + 1x1 ----
__global__ __launch_bounds__(256) void stage1_kernel(
    const float* __restrict__ cen, const float* __restrict__ w_conv,
    const float* __restrict__ gamma, const float* __restrict__ beta,
    const float* __restrict__ mean, const float* __restrict__ var,
    const float* __restrict__ w1x1, const float* __restrict__ b1x1) {
    extern __shared__ __align__(128) char smem[];
    float* biasS = (float*)(smem + OFF_BIAS);
    float* w1S = (float*)(smem + OFF_W1);
    float* b1S = (float*)(smem + OFF_B1);

    const int t = threadIdx.x;
    const int lane = t & 31;
    const int wrp = t >> 5;
    const int x0 = blockIdx.x * 128;
    const int y0 = blockIdx.y * 32;
    const int b = blockIdx.z;
    const uint32_t sbase = smem_u32(smem);

    // weights (BN-folded, fp16 hi/lo) -> WB[co][pos*32+ci]
    for (int i = t; i < C * C * 9; i += 256) {
        int co = i / 288;
        int rem = i - co * 288;
        int ci = rem / 9;
        int pos = rem - ci * 9;
        float inv = __ldg(&gamma[co]) * rsqrtf(__ldg(&var[co]) + 1e-5f);
        float w = __ldg(&w_conv[i]) * inv;
        __half hb = __float2half(w);
        __half lb = __float2half(w - __half2float(hb));
        char* p = smem + OFF_WB + co * WB_STRIDE + (pos * 32 + ci) * 2;
        *reinterpret_cast<__half*>(p) = hb;
        *reinterpret_cast<__half*>(p + 576) = lb;
    }
    if (t < C) {
        float inv = __ldg(&gamma[t]) * rsqrtf(__ldg(&var[t]) + 1e-5f);
        biasS[t] = __ldg(&beta[t]) - __ldg(&mean[t]) * inv;
        w1S[t] = __ldg(&w1x1[t]);
    }
    if (t == 0) b1S[0] = __ldg(b1x1);

    // preload rows y0-1 .. y0+2
    {
        float va[17];
#pragma unroll
        for (int rr = 0; rr < 4; rr++) {
            ldg_row(cen, b, y0 - 1 + rr, x0, t, va);
            sts_row(smem, y0 - 1 + rr, t, va);
        }
    }
    __syncthreads();

    // per-warp geometry: row r = wrp>>2, px0 = (wrp&3)*32
    const int r = wrp >> 2;
    const int px0 = (wrp & 3) * 32;

    // lane-invariant ldmatrix address pieces
    const uint32_t aLane = (uint32_t)((px0 + (lane & 15)) * A_XSTR + ((lane & 16) ? 16 : 0));
    const uint32_t bLane = sbase + OFF_WB +
                           (uint32_t)(((lane & 7) + ((lane & 16) ? 8 : 0)) * WB_STRIDE +
                                      ((lane & 8) ? 16 : 0));
    const int g = lane >> 2;
    const int tid4 = lane & 3;

    for (int y = y0; y < y0 + 32; y += 2) {
        // prefetch rows y+3, y+4 into registers (hidden under MMA)
        float va[17], vb[17];
        ldg_row(cen, b, y + 3, x0, t, va);
        ldg_row(cen, b, y + 4, x0, t, vb);

        float Cfr[2][4][4];
#pragma unroll
        for (int mt = 0; mt < 2; mt++)
#pragma unroll
            for (int nt = 0; nt < 4; nt++)
#pragma unroll
                for (int q = 0; q < 4; q++) Cfr[mt][nt][q] = 0.f;

        const int yr = y + r;
#pragma unroll
        for (int kh = 0; kh < 3; kh++) {
            const uint32_t aRing = sbase + ((yr - 1 + kh + 6) % 6) * A_SLOT + aLane;
#pragma unroll
            for (int kw = 0; kw < 3; kw++) {
                const int pos = kh * 3 + kw;
                const uint32_t aBase = aRing + kw * A_XSTR;
                const uint32_t bBase = bLane + pos * 64;
#pragma unroll
                for (int cih = 0; cih < 2; cih++) {
                    uint32_t Ah[2][4], Bh[8], Bl[8];
                    const uint32_t aOff = aBase + cih * 32;
#pragma unroll
                    for (int mt = 0; mt < 2; mt++)
                        ldsm_x4(aOff + mt * (16 * A_XSTR), Ah[mt][0], Ah[mt][1],
                                Ah[mt][2], Ah[mt][3]);
                    const uint32_t bOff = bBase + cih * 32;
                    ldsm_x4(bOff, Bh[0], Bh[1], Bh[2], Bh[3]);
                    ldsm_x4(bOff + 16 * WB_STRIDE, Bh[4], Bh[5], Bh[6], Bh[7]);
                    ldsm_x4(bOff + 576, Bl[0], Bl[1], Bl[2], Bl[3]);
                    ldsm_x4(bOff + 576 + 16 * WB_STRIDE, Bl[4], Bl[5], Bl[6], Bl[7]);
#pragma unroll
                    for (int mt = 0; mt < 2; mt++)
#pragma unroll
                        for (int nt = 0; nt < 4; nt++)
                            mma_f16(Cfr[mt][nt], Ah[mt], Bh[nt * 2], Bh[nt * 2 + 1]);
#pragma unroll
                    for (int mt = 0; mt < 2; mt++)
#pragma unroll
                        for (int nt = 0; nt < 4; nt++)
                            mma_f16(Cfr[mt][nt], Ah[mt], Bl[nt * 2], Bl[nt * 2 + 1]);
                }
            }
        }

        // epilogue: bias + SiLU + 1x1 dot over co, quad-lane reduce
        const float b1v = b1S[0];
#pragma unroll
        for (int mt = 0; mt < 2; mt++) {
            float sA = 0.f, sB = 0.f;
#pragma unroll
            for (int nt = 0; nt < 4; nt++) {
                int co0 = nt * 8 + 2 * tid4;
                float bs0 = biasS[co0], bs1 = biasS[co0 + 1];
                float w10 = w1S[co0], w11 = w1S[co0 + 1];
                float v0 = Cfr[mt][nt][0] + bs0;
                float v1 = Cfr[mt][nt][1] + bs1;
                float v2 = Cfr[mt][nt][2] + bs0;
                float v3 = Cfr[mt][nt][3] + bs1;
                sA = fmaf(w10, __fdividef(v0, 1.f + __expf(-v0)), sA);
                sA = fmaf(w11, __fdividef(v1, 1.f + __expf(-v1)), sA);
                sB = fmaf(w10, __fdividef(v2, 1.f + __expf(-v2)), sB);
                sB = fmaf(w11, __fdividef(v3, 1.f + __expf(-v3)), sB);
            }
            sA += __shfl_xor_sync(0xFFFFFFFF, sA, 1);
            sA += __shfl_xor_sync(0xFFFFFFFF, sA, 2);
            sB += __shfl_xor_sync(0xFFFFFFFF, sB, 1);
            sB += __shfl_xor_sync(0xFFFFFFFF, sB, 2);
            if (tid4 == 0) {
                int px = px0 + mt * 16;
                float* gp = &g_x[((size_t)b * H + yr) * W + x0 + px];
                gp[g] = sA + b1v;
                gp[g + 8] = sB + b1v;
            }
        }

        // commit prefetched rows to ring
        sts_row(smem, y + 3, t, va);
        sts_row(smem, y + 4, t, vb);
        __syncthreads();
    }
}

// ---- K2: shifted-difference attention + gate all channels ----
__device__ __forceinline__ float ldx(const float* __restrict__ X, int i, int j) {
    if ((unsigned)i < (unsigned)H && (unsigned)j < (unsigned)W)
        return __ldg(X + i * W + j);
    return 0.f;
}

__global__ __launch_bounds__(128) void stage2_kernel(
    const float* __restrict__ cen, float* __restrict__ out) {
    const int i = blockIdx.x;
    const int b = blockIdx.y;
    const int j0 = threadIdx.x * 4;
    const float* X = g_x + (size_t)b * H * W;

    float4 av;
    float* avp = (float*)&av;
#pragma unroll
    for (int p = 0; p < 4; p++) {
        int j = j0 + p;
        float x0 = X[i * W + j];
        float ms[2];
#pragma unroll
        for (int si = 0; si < 2; si++) {
            int s = si ? 3 : 1;
            float p0 = (x0 - ldx(X, i - s, j - s)) * (x0 - ldx(X, i + s, j + s));
            float p1 = (x0 - ldx(X, i - s, j)) * (x0 - ldx(X, i + s, j));
            float p2 = (x0 - ldx(X, i - s, j + s)) * (x0 - ldx(X, i + s, j - s));
            float p3 = (x0 - ldx(X, i, j - s)) * (x0 - ldx(X, i, j + s));
            ms[si] = fminf(fminf(p0, p1), fminf(p2, p3));
        }
        float att_in = (fmaxf(ms[0], ms[1]) + 0.5f * (ms[0] + ms[1])) * 0.5f;
        float rr = fmaxf(att_in, 0.f);
        avp[p] = 1.f / (1.f + __expf(-rr));
    }

    size_t base = ((size_t)b * C * H + i) * W + j0;
#pragma unroll
    for (int c = 0; c < C; c++) {
        const float4 v = *(const float4*)(cen + base + (size_t)c * H * W);
        float4 o;
        o.x = v.x * av.x;
        o.y = v.y * av.y;
        o.z = v.z * av.z;
        o.w = v.w * av.w;
        *(float4*)(out + base + (size_t)c * H * W) = o;
    }
}

extern "C" void kernel_launch(void* const* d_in, const int* in_sizes, int n_in,
                              void* d_out, int out_size) {
    const float* cen = (const float*)d_in[0];
    const float* w_conv = (const float*)d_in[1];
    const float* gamma = (const float*)d_in[2];
    const float* beta = (const float*)d_in[3];
    const float* mean = (const float*)d_in[4];
    const float* var = (const float*)d_in[5];
    const float* w1x1 = (const float*)d_in[6];
    const float* b1x1 = (const float*)d_in[7];
    float* out = (float*)d_out;

    cudaFuncSetAttribute(stage1_kernel, cudaFuncAttributeMaxDynamicSharedMemorySize,
                         SMEM_TOTAL);

    stage1_kernel<<<dim3(4, 16, BATCH), 256, SMEM_TOTAL>>>(cen, w_conv, gamma, beta,
                                                           mean, var, w1x1, b1x1);
    stage2_kernel<<<dim3(H, BATCH), 128>>>(cen, out);
}